// round 2
// baseline (speedup 1.0000x reference)
#include <cuda_runtime.h>

#define NN   50000
#define DEG  16
#define DIM  128
#define EDIM 32
#define HDIM 256   // 2*DIM
#define NPB  8     // nodes per block in edge kernel

// ---- scratch (device globals; no allocation allowed) ----
__device__ float g_P[NN * 512];    // [N,512]: 0..255 = P_s = x@We1[0:128], 256..511 = P_r
__device__ float g_S[NN * HDIM];   // [N,256]: sum over 16 edges of swish(h_pre)
__device__ float g_AGG[NN * DIM];  // [N,128]: LN'd aggregated messages
__device__ float g_U[NN * HDIM];   // [N,256]: swish hidden of node MLP

typedef unsigned long long u64;

__device__ __forceinline__ void ffma2(u64& d, u64 a, u64 b) {
    asm("fma.rn.f32x2 %0, %1, %2, %3;" : "=l"(d) : "l"(a), "l"(b), "l"(d));
}
__device__ __forceinline__ u64 packf2(float lo, float hi) {
    u64 r; asm("mov.b64 %0, {%1, %2};" : "=l"(r) : "f"(lo), "f"(hi)); return r;
}
__device__ __forceinline__ float2 unpackf2(u64 v) {
    float2 r; asm("mov.b64 {%0, %1}, %2;" : "=f"(r.x), "=f"(r.y) : "l"(v)); return r;
}
__device__ __forceinline__ u64 addf2(u64 a, u64 b) {
    u64 r; asm("add.rn.f32x2 %0, %1, %2;" : "=l"(r) : "l"(a), "l"(b)); return r;
}
__device__ __forceinline__ float swishf(float v) {
    return __fdividef(v, 1.0f + __expf(-v));
}

// ============================================================================
// Register-tiled GEMM with packed f32x2 FMA.
//   C[M,NC] = A[M,K] @ B[K,NC]  + fused epilogue
//   MODE 0: plain store (ldOut/outOff)        [NC=256]
//   MODE 1: val=acc*scale+bias; LN*mask       [NC=128]
//   MODE 2: val=swish(acc+bias); A=concat     [NC=256]
//   MODE 3: val=acc+bias+resid; LN*mask       [NC=128]
// 256 threads. BM=64 rows/block. warp w owns rows w*8..w*8+7 (all NC cols in warp).
// Thread (warp, lane): rows warp*8+0..7, cols lane*TN..lane*TN+TN-1, TN=NC/32.
// A smem transposed (k-major) -> row pairs read directly as packed doubles.
// B smem stored pre-duplicated (b,b) doubles.
// ============================================================================
template<int K, int NC, int MODE>
__global__ void __launch_bounds__(256) gemm_fused(
    const float* __restrict__ A0, const float* __restrict__ A1,
    const float* __restrict__ B,
    const float* __restrict__ bias, float scale,
    const float* __restrict__ gamma, const float* __restrict__ beta,
    const float* __restrict__ mask, const float* __restrict__ resid,
    float* __restrict__ out, int ldOut, int outOff)
{
    constexpr int BM = 64;
    constexpr int BK = 16;
    constexpr int TN = NC / 32;        // 4 or 8
    constexpr int APAD = 4;            // float pad -> 16B-aligned rows, low conflicts
    constexpr bool LN = (MODE == 1 || MODE == 3);

    __shared__ __align__(16) float Asm[BK][BM + APAD];
    __shared__ __align__(16) u64   Bd[BK * NC];          // duplicated-pair B tile

    const int t    = threadIdx.x;
    const int lane = t & 31;
    const int warp = t >> 5;
    const int n0   = blockIdx.x * BM;

    u64 acc[4][TN];
    #pragma unroll
    for (int p = 0; p < 4; p++)
        #pragma unroll
        for (int j = 0; j < TN; j++) acc[p][j] = 0ull;

    const int ar = t >> 2;        // row in tile for A load (0..63)
    const int akq = t & 3;        // which float4 along k

    for (int kb = 0; kb < K; kb += BK) {
        // ---- stage A tile (transposed) ----
        {
            int row = n0 + ar;
            float4 a4 = make_float4(0.f, 0.f, 0.f, 0.f);
            if (row < NN) {
                int gk = kb + akq * 4;
                if (MODE == 2) {
                    a4 = (gk < DIM)
                       ? *reinterpret_cast<const float4*>(&A0[row * DIM + gk])
                       : *reinterpret_cast<const float4*>(&A1[row * DIM + (gk - DIM)]);
                } else {
                    a4 = *reinterpret_cast<const float4*>(&A0[row * K + gk]);
                }
            }
            Asm[akq * 4 + 0][ar] = a4.x;
            Asm[akq * 4 + 1][ar] = a4.y;
            Asm[akq * 4 + 2][ar] = a4.z;
            Asm[akq * 4 + 3][ar] = a4.w;
        }
        // ---- stage B tile, duplicated pairs ----
        {
            constexpr int TOT4 = (BK * NC) / 4;   // float4 count
            #pragma unroll
            for (int i = t; i < TOT4; i += 256) {
                int fi = i * 4;
                int k = fi / NC, c = fi % NC;
                float4 b4 = *reinterpret_cast<const float4*>(&B[(kb + k) * NC + c]);
                u64* dst = &Bd[k * NC + c];
                dst[0] = packf2(b4.x, b4.x);
                dst[1] = packf2(b4.y, b4.y);
                dst[2] = packf2(b4.z, b4.z);
                dst[3] = packf2(b4.w, b4.w);
            }
        }
        __syncthreads();

        #pragma unroll
        for (int kk = 0; kk < BK; kk++) {
            const ulonglong2* ap =
                reinterpret_cast<const ulonglong2*>(&Asm[kk][warp * 8]);
            ulonglong2 a01 = ap[0];   // rows (0,1),(2,3)
            ulonglong2 a23 = ap[1];   // rows (4,5),(6,7)
            u64 apair[4] = {a01.x, a01.y, a23.x, a23.y};

            const ulonglong2* bp =
                reinterpret_cast<const ulonglong2*>(&Bd[kk * NC + lane * TN]);
            u64 bdup[TN];
            #pragma unroll
            for (int q = 0; q < TN / 2; q++) {
                ulonglong2 bb = bp[q];
                bdup[2 * q] = bb.x; bdup[2 * q + 1] = bb.y;
            }
            #pragma unroll
            for (int p = 0; p < 4; p++)
                #pragma unroll
                for (int j = 0; j < TN; j++)
                    ffma2(acc[p][j], apair[p], bdup[j]);
        }
        __syncthreads();
    }

    // ------------------ epilogue ------------------
    const int c0 = lane * TN;

    if (MODE == 0) {
        #pragma unroll
        for (int p = 0; p < 4; p++) {
            #pragma unroll
            for (int h = 0; h < 2; h++) {
                int row = n0 + warp * 8 + 2 * p + h;
                if (row < NN) {
                    float* o = &out[row * ldOut + outOff + c0];
                    #pragma unroll
                    for (int j = 0; j < TN; j++) {
                        float2 v = unpackf2(acc[p][j]);
                        o[j] = h ? v.y : v.x;
                    }
                }
            }
        }
        return;
    }
    if (MODE == 2) {
        float be[TN];
        #pragma unroll
        for (int j = 0; j < TN; j++) be[j] = bias[c0 + j];
        #pragma unroll
        for (int p = 0; p < 4; p++) {
            #pragma unroll
            for (int h = 0; h < 2; h++) {
                int row = n0 + warp * 8 + 2 * p + h;
                if (row < NN) {
                    float* o = &out[row * ldOut + c0];
                    #pragma unroll
                    for (int j = 0; j < TN; j++) {
                        float2 v = unpackf2(acc[p][j]);
                        o[j] = swishf((h ? v.y : v.x) + be[j]);
                    }
                }
            }
        }
        return;
    }
    if (LN) {
        // NC == 128, TN == 4. Each warp owns 8 complete rows.
        float be[TN], gm[TN], bt[TN];
        #pragma unroll
        for (int j = 0; j < TN; j++) {
            be[j] = bias[c0 + j]; gm[j] = gamma[c0 + j]; bt[j] = beta[c0 + j];
        }
        float val[8][TN];
        #pragma unroll
        for (int p = 0; p < 4; p++) {
            #pragma unroll
            for (int j = 0; j < TN; j++) {
                float2 v = unpackf2(acc[p][j]);
                val[2 * p][j]     = v.x * scale + be[j];
                val[2 * p + 1][j] = v.y * scale + be[j];
            }
        }
        if (MODE == 3) {
            #pragma unroll
            for (int r = 0; r < 8; r++) {
                int row = n0 + warp * 8 + r;
                if (row < NN) {
                    float4 rs = *reinterpret_cast<const float4*>(&resid[row * NC + c0]);
                    val[r][0] += rs.x; val[r][1] += rs.y;
                    val[r][2] += rs.z; val[r][3] += rs.w;
                }
            }
        }
        #pragma unroll
        for (int r = 0; r < 8; r++) {
            int row = n0 + warp * 8 + r;
            float s = val[r][0] + val[r][1] + val[r][2] + val[r][3];
            float s2 = val[r][0] * val[r][0] + val[r][1] * val[r][1]
                     + val[r][2] * val[r][2] + val[r][3] * val[r][3];
            #pragma unroll
            for (int o = 16; o > 0; o >>= 1) {
                s  += __shfl_xor_sync(0xffffffffu, s,  o);
                s2 += __shfl_xor_sync(0xffffffffu, s2, o);
            }
            float m = s * (1.0f / 128.0f);
            float var = s2 * (1.0f / 128.0f) - m * m;
            float rstd = rsqrtf(var + 1e-5f);
            if (row < NN) {
                float mk = mask[row];
                float4 o4;
                o4.x = ((val[r][0] - m) * rstd * gm[0] + bt[0]) * mk;
                o4.y = ((val[r][1] - m) * rstd * gm[1] + bt[1]) * mk;
                o4.z = ((val[r][2] - m) * rstd * gm[2] + bt[2]) * mk;
                o4.w = ((val[r][3] - m) * rstd * gm[3] + bt[3]) * mk;
                *reinterpret_cast<float4*>(&out[row * NC + c0]) = o4;
            }
        }
    }
}

// ============================================================================
// Edge kernel (f32x2 over edge pairs):
//   h_e = swish(P_s[senders[e]] + P_r[n] + ef[e]@We1[256:288] + be1)
//   S[n] = sum_e h_e      (16 contiguous edges per node)
// 256 threads = 256 output channels; NPB nodes per block.
// Edge features pre-packed into (even-edge, odd-edge) f32x2 pairs in smem;
// compute reads are broadcast (all channels use same pair data).
// ============================================================================
__global__ void __launch_bounds__(256, 2) edge_kernel(
    const float* __restrict__ edge_feat, const int* __restrict__ senders,
    const float* __restrict__ We1, const float* __restrict__ be1)
{
    __shared__ __align__(16) u64 efp[NPB * (DEG / 2) * EDIM];  // 16 KB, pair-packed
    __shared__ int snd[NPB * DEG];

    const int t  = threadIdx.x;
    const int n0 = blockIdx.x * NPB;
    const int cnt = min(NPB, NN - n0);
    const int e0 = n0 * DEG;

    // load edge features, pack edge pairs into f32x2 lanes
    {
        const int totf = cnt * DEG * EDIM;
        float* efs = reinterpret_cast<float*>(efp);
        for (int j = t; j < totf; j += 256) {
            int el = j / EDIM, k = j % EDIM;
            int pg = el >> 1, half = el & 1;
            efs[(pg * EDIM + k) * 2 + half] = edge_feat[e0 * EDIM + j];
        }
        for (int j = t; j < cnt * DEG; j += 256) snd[j] = senders[e0 + j];
    }

    // duplicated weight column for this channel: w2[k] = (w[k], w[k])
    u64 w2[EDIM];
    #pragma unroll
    for (int k = 0; k < EDIM; k++) {
        float w = We1[(HDIM + k) * HDIM + t];
        w2[k] = packf2(w, w);
    }
    const float b1 = be1[t];
    __syncthreads();

    for (int ni = 0; ni < cnt; ni++) {
        const int n = n0 + ni;
        const float pr = g_P[n * 512 + 256 + t] + b1;
        const u64 prd = packf2(pr, pr);

        // prefetch all 16 sender projections (MLP=16 hides L2 latency)
        float fv[DEG];
        #pragma unroll
        for (int e = 0; e < DEG; e++)
            fv[e] = g_P[(size_t)snd[ni * DEG + e] * 512 + t];

        float sacc = 0.0f;
        #pragma unroll
        for (int p = 0; p < DEG / 2; p++) {
            u64 v2 = addf2(prd, packf2(fv[2 * p], fv[2 * p + 1]));
            const ulonglong2* ep =
                reinterpret_cast<const ulonglong2*>(&efp[(ni * (DEG / 2) + p) * EDIM]);
            #pragma unroll
            for (int q = 0; q < EDIM / 2; q++) {
                ulonglong2 e2 = ep[q];
                ffma2(v2, e2.x, w2[2 * q]);
                ffma2(v2, e2.y, w2[2 * q + 1]);
            }
            float2 v = unpackf2(v2);
            sacc += swishf(v.x) + swishf(v.y);
        }
        g_S[n * HDIM + t] = sacc;
    }
}

// ============================================================================
extern "C" void kernel_launch(void* const* d_in, const int* in_sizes, int n_in,
                              void* d_out, int out_size)
{
    const float* node_inp  = (const float*)d_in[0];
    const float* edge_feat = (const float*)d_in[1];
    const float* node_mask = (const float*)d_in[2];
    const float* We1       = (const float*)d_in[3];
    const float* be1       = (const float*)d_in[4];
    const float* We2       = (const float*)d_in[5];
    const float* be2       = (const float*)d_in[6];
    const float* g_msg     = (const float*)d_in[7];
    const float* b_msg     = (const float*)d_in[8];
    const float* Wn1       = (const float*)d_in[9];
    const float* bn1       = (const float*)d_in[10];
    const float* Wn2       = (const float*)d_in[11];
    const float* bn2       = (const float*)d_in[12];
    const float* g_node    = (const float*)d_in[13];
    const float* b_node    = (const float*)d_in[14];
    const int*   senders   = (const int*)d_in[15];
    float* out = (float*)d_out;

    float *Pp, *Sp, *AGGp, *Up;
    cudaGetSymbolAddress((void**)&Pp,   g_P);
    cudaGetSymbolAddress((void**)&Sp,   g_S);
    cudaGetSymbolAddress((void**)&AGGp, g_AGG);
    cudaGetSymbolAddress((void**)&Up,   g_U);

    const dim3 gRows((NN + 63) / 64);

    // 1) per-node projections: P_s = x @ We1[0:128], P_r = x @ We1[128:256]
    gemm_fused<128, 256, 0><<<gRows, 256>>>(
        node_inp, nullptr, We1,
        nullptr, 1.0f, nullptr, nullptr, nullptr, nullptr, Pp, 512, 0);
    gemm_fused<128, 256, 0><<<gRows, 256>>>(
        node_inp, nullptr, We1 + 128 * 256,
        nullptr, 1.0f, nullptr, nullptr, nullptr, nullptr, Pp, 512, 256);

    // 2) per-edge swish + segment sum -> S[N,256]
    edge_kernel<<<(NN + NPB - 1) / NPB, 256>>>(edge_feat, senders, We1, be1);

    // 3) agg = LN(S @ We2 / 16 + be2; g_msg, b_msg) * mask
    gemm_fused<256, 128, 1><<<gRows, 256>>>(
        Sp, nullptr, We2,
        be2, 1.0f / 16.0f, g_msg, b_msg, node_mask, nullptr, AGGp, 128, 0);

    // 4) U = swish([node_inp, agg] @ Wn1 + bn1)
    gemm_fused<256, 256, 2><<<gRows, 256>>>(
        node_inp, AGGp, Wn1,
        bn1, 1.0f, nullptr, nullptr, nullptr, nullptr, Up, 256, 0);

    // 5) out = LN(node_inp + U @ Wn2 + bn2; g_node, b_node) * mask
    gemm_fused<256, 128, 3><<<gRows, 256>>>(
        Up, nullptr, Wn2,
        bn2, 1.0f, g_node, b_node, node_mask, node_inp, out, 128, 0);
}

// round 3
// speedup vs baseline: 1.7691x; 1.7691x over previous
#include <cuda_runtime.h>

#define NN   50000
#define DEG  16
#define DIM  128
#define EDIM 32
#define HDIM 256   // 2*DIM
#define NPB  8     // nodes per block in edge kernel

// ---- scratch (device globals; no allocation allowed) ----
__device__ float g_P[NN * 512];    // [N,512]: 0..255 = P_s = x@We1[0:128], 256..511 = P_r
__device__ float g_S[NN * HDIM];   // [N,256]: sum over 16 edges of swish(h_pre)
__device__ float g_AGG[NN * DIM];  // [N,128]: LN'd aggregated messages
__device__ float g_U[NN * HDIM];   // [N,256]: swish hidden of node MLP

__device__ __forceinline__ float swishf(float v) {
    return __fdividef(v, 1.0f + __expf(-v));
}

// ============================================================================
// Register-tiled SGEMM, 8x8 per thread. C[M,NC] = A[M,K] @ B[K,NC] + epilogue.
//   BM=128 rows/block, 128 cols/block (grid.y covers NC/128), BK=16.
//   256 threads: ty=tid>>4 (row group), tx=tid&15 (col group).
//   MODE 0: plain store (ldOut/outOff)
//   MODE 1: val=acc*scale+bias; LN(gamma,beta)*mask    [NC=128 only]
//   MODE 2: val=swish(acc+bias); A=concat(A0,A1) on K
//   MODE 3: val=acc+bias+resid; LN(gamma,beta)*mask    [NC=128 only]
// ============================================================================
template<int K, int MODE>
__global__ void __launch_bounds__(256, 2) gemm_fused(
    const float* __restrict__ A0, const float* __restrict__ A1,
    const float* __restrict__ B, int ldB,
    const float* __restrict__ bias, float scale,
    const float* __restrict__ gamma, const float* __restrict__ beta,
    const float* __restrict__ mask, const float* __restrict__ resid,
    float* __restrict__ out, int ldOut, int outOff)
{
    constexpr int BM = 128;
    constexpr int BK = 16;

    __shared__ __align__(16) float Asm[BK][BM + 4];   // transposed A tile
    __shared__ __align__(16) float Bsm[BK][128];

    const int tid  = threadIdx.x;
    const int ty   = tid >> 4;        // 0..15
    const int tx   = tid & 15;        // 0..15
    const int n0   = blockIdx.x * BM;
    const int coff = blockIdx.y * 128;

    float acc[8][8];
    #pragma unroll
    for (int r = 0; r < 8; r++)
        #pragma unroll
        for (int j = 0; j < 8; j++) acc[r][j] = 0.0f;

    for (int kb = 0; kb < K; kb += BK) {
        // ---- stage A (transposed): 512 float4, 2 per thread ----
        #pragma unroll
        for (int s = 0; s < 2; s++) {
            int idx = tid + s * 256;
            int row = idx >> 2, q = idx & 3;
            int grow = n0 + row;
            float4 a4 = make_float4(0.f, 0.f, 0.f, 0.f);
            if (grow < NN) {
                int gk = kb + q * 4;
                if (MODE == 2)
                    a4 = (gk < DIM)
                       ? *reinterpret_cast<const float4*>(&A0[grow * DIM + gk])
                       : *reinterpret_cast<const float4*>(&A1[grow * DIM + (gk - DIM)]);
                else
                    a4 = *reinterpret_cast<const float4*>(&A0[grow * K + gk]);
            }
            Asm[q * 4 + 0][row] = a4.x;
            Asm[q * 4 + 1][row] = a4.y;
            Asm[q * 4 + 2][row] = a4.z;
            Asm[q * 4 + 3][row] = a4.w;
        }
        // ---- stage B: 512 float4, 2 per thread ----
        #pragma unroll
        for (int s = 0; s < 2; s++) {
            int idx = tid + s * 256;
            int k = idx >> 5, c4 = idx & 31;
            float4 b4 = *reinterpret_cast<const float4*>(&B[(kb + k) * ldB + coff + c4 * 4]);
            *reinterpret_cast<float4*>(&Bsm[k][c4 * 4]) = b4;
        }
        __syncthreads();

        #pragma unroll
        for (int kk = 0; kk < BK; kk++) {
            float4 a0 = *reinterpret_cast<const float4*>(&Asm[kk][ty * 8]);
            float4 a1 = *reinterpret_cast<const float4*>(&Asm[kk][ty * 8 + 4]);
            float4 b0 = *reinterpret_cast<const float4*>(&Bsm[kk][tx * 8]);
            float4 b1 = *reinterpret_cast<const float4*>(&Bsm[kk][tx * 8 + 4]);
            float ar[8] = {a0.x, a0.y, a0.z, a0.w, a1.x, a1.y, a1.z, a1.w};
            float br[8] = {b0.x, b0.y, b0.z, b0.w, b1.x, b1.y, b1.z, b1.w};
            #pragma unroll
            for (int r = 0; r < 8; r++)
                #pragma unroll
                for (int j = 0; j < 8; j++)
                    acc[r][j] += ar[r] * br[j];
        }
        __syncthreads();
    }

    // ------------------ epilogue ------------------
    const int cbase = coff + tx * 8;

    if (MODE == 0) {
        #pragma unroll
        for (int r = 0; r < 8; r++) {
            int row = n0 + ty * 8 + r;
            if (row < NN) {
                float* o = &out[(size_t)row * ldOut + outOff + cbase];
                *reinterpret_cast<float4*>(o)     = make_float4(acc[r][0], acc[r][1], acc[r][2], acc[r][3]);
                *reinterpret_cast<float4*>(o + 4) = make_float4(acc[r][4], acc[r][5], acc[r][6], acc[r][7]);
            }
        }
        return;
    }
    if (MODE == 2) {
        float be[8];
        #pragma unroll
        for (int j = 0; j < 8; j++) be[j] = bias[cbase + j];
        #pragma unroll
        for (int r = 0; r < 8; r++) {
            int row = n0 + ty * 8 + r;
            if (row < NN) {
                float v[8];
                #pragma unroll
                for (int j = 0; j < 8; j++) v[j] = swishf(acc[r][j] + be[j]);
                float* o = &out[(size_t)row * ldOut + cbase];
                *reinterpret_cast<float4*>(o)     = make_float4(v[0], v[1], v[2], v[3]);
                *reinterpret_cast<float4*>(o + 4) = make_float4(v[4], v[5], v[6], v[7]);
            }
        }
        return;
    }
    // LN modes (NC=128, coff=0): 16 tx-threads cover the full 128-wide row.
    {
        float be[8], gm[8], bt[8];
        #pragma unroll
        for (int j = 0; j < 8; j++) {
            be[j] = bias[cbase + j]; gm[j] = gamma[cbase + j]; bt[j] = beta[cbase + j];
        }
        #pragma unroll
        for (int r = 0; r < 8; r++) {
            int row = n0 + ty * 8 + r;
            float v[8];
            #pragma unroll
            for (int j = 0; j < 8; j++) v[j] = acc[r][j] * scale + be[j];
            if (MODE == 3 && row < NN) {
                float4 r0 = *reinterpret_cast<const float4*>(&resid[(size_t)row * 128 + cbase]);
                float4 r1 = *reinterpret_cast<const float4*>(&resid[(size_t)row * 128 + cbase + 4]);
                v[0] += r0.x; v[1] += r0.y; v[2] += r0.z; v[3] += r0.w;
                v[4] += r1.x; v[5] += r1.y; v[6] += r1.z; v[7] += r1.w;
            }
            float s = 0.f, s2 = 0.f;
            #pragma unroll
            for (int j = 0; j < 8; j++) { s += v[j]; s2 += v[j] * v[j]; }
            #pragma unroll
            for (int o = 8; o > 0; o >>= 1) {
                s  += __shfl_xor_sync(0xffffffffu, s,  o);
                s2 += __shfl_xor_sync(0xffffffffu, s2, o);
            }
            float m    = s * (1.0f / 128.0f);
            float var  = s2 * (1.0f / 128.0f) - m * m;
            float rstd = rsqrtf(var + 1e-5f);
            if (row < NN) {
                float mk = mask[row];
                float w[8];
                #pragma unroll
                for (int j = 0; j < 8; j++)
                    w[j] = ((v[j] - m) * rstd * gm[j] + bt[j]) * mk;
                float* o = &out[(size_t)row * 128 + cbase];
                *reinterpret_cast<float4*>(o)     = make_float4(w[0], w[1], w[2], w[3]);
                *reinterpret_cast<float4*>(o + 4) = make_float4(w[4], w[5], w[6], w[7]);
            }
        }
    }
}

// ============================================================================
// Edge kernel, 2 channels/thread:
//   h_e = swish(P_s[senders[e]] + P_r[n] + ef[e]@We1[256:288] + be1)
//   S[n] = sum_e h_e   (16 contiguous edges per node; receivers=repeat(arange,16))
// 256 threads: p=t>>7 picks node half (4 nodes each), c2=t&127 -> channels 2c2,2c2+1.
// ef tile broadcast from smem; sender projections gathered as float2 (8-deep MLP).
// ============================================================================
__global__ void __launch_bounds__(256, 2) edge_kernel(
    const float* __restrict__ edge_feat, const int* __restrict__ senders,
    const float* __restrict__ We1, const float* __restrict__ be1)
{
    __shared__ __align__(16) float ef[NPB * DEG * EDIM];  // 16 KB
    __shared__ int snd[NPB * DEG];

    const int t  = threadIdx.x;
    const int p  = t >> 7;         // node-half
    const int c2 = t & 127;        // channel pair id
    const int ch = c2 * 2;
    const int n0 = blockIdx.x * NPB;
    const int e0 = n0 * DEG;

    // stage edge features (straight copy, coalesced) + senders
    {
        const float4* src = reinterpret_cast<const float4*>(edge_feat + (size_t)e0 * EDIM);
        float4* dst = reinterpret_cast<float4*>(ef);
        #pragma unroll
        for (int s = 0; s < 4; s++) dst[t + s * 256] = src[t + s * 256];
        if (t < NPB * DEG) snd[t] = senders[e0 + t];
    }

    // weight columns (ch, ch+1) for the 32 edge-feature rows of We1
    float2 w[EDIM];
    #pragma unroll
    for (int k = 0; k < EDIM; k++)
        w[k] = *reinterpret_cast<const float2*>(&We1[(size_t)(HDIM + k) * HDIM + ch]);
    const float2 b2 = *reinterpret_cast<const float2*>(&be1[ch]);
    __syncthreads();

    #pragma unroll
    for (int q = 0; q < 4; q++) {
        const int ni = p * 4 + q;
        const int n  = n0 + ni;
        float2 pr = *reinterpret_cast<const float2*>(&g_P[(size_t)n * 512 + 256 + ch]);
        pr.x += b2.x; pr.y += b2.y;

        float2 sacc = make_float2(0.f, 0.f);
        #pragma unroll
        for (int half = 0; half < 2; half++) {
            // prefetch 8 sender projections (float2 L2 gathers)
            float2 fv[8];
            #pragma unroll
            for (int e = 0; e < 8; e++) {
                int s = snd[ni * DEG + half * 8 + e];
                fv[e] = *reinterpret_cast<const float2*>(&g_P[(size_t)s * 512 + ch]);
            }
            #pragma unroll
            for (int e = 0; e < 8; e++) {
                float vx = pr.x + fv[e].x;
                float vy = pr.y + fv[e].y;
                const float4* ep = reinterpret_cast<const float4*>(
                    &ef[(ni * DEG + half * 8 + e) * EDIM]);
                #pragma unroll
                for (int g = 0; g < 8; g++) {
                    float4 f = ep[g];
                    vx += f.x * w[4*g+0].x + f.y * w[4*g+1].x
                        + f.z * w[4*g+2].x + f.w * w[4*g+3].x;
                    vy += f.x * w[4*g+0].y + f.y * w[4*g+1].y
                        + f.z * w[4*g+2].y + f.w * w[4*g+3].y;
                }
                sacc.x += swishf(vx);
                sacc.y += swishf(vy);
            }
        }
        *reinterpret_cast<float2*>(&g_S[(size_t)n * HDIM + ch]) = sacc;
    }
}

// ============================================================================
extern "C" void kernel_launch(void* const* d_in, const int* in_sizes, int n_in,
                              void* d_out, int out_size)
{
    const float* node_inp  = (const float*)d_in[0];
    const float* edge_feat = (const float*)d_in[1];
    const float* node_mask = (const float*)d_in[2];
    const float* We1       = (const float*)d_in[3];
    const float* be1       = (const float*)d_in[4];
    const float* We2       = (const float*)d_in[5];
    const float* be2       = (const float*)d_in[6];
    const float* g_msg     = (const float*)d_in[7];
    const float* b_msg     = (const float*)d_in[8];
    const float* Wn1       = (const float*)d_in[9];
    const float* bn1       = (const float*)d_in[10];
    const float* Wn2       = (const float*)d_in[11];
    const float* bn2       = (const float*)d_in[12];
    const float* g_node    = (const float*)d_in[13];
    const float* b_node    = (const float*)d_in[14];
    const int*   senders   = (const int*)d_in[15];
    float* out = (float*)d_out;

    float *Pp, *Sp, *AGGp, *Up;
    cudaGetSymbolAddress((void**)&Pp,   g_P);
    cudaGetSymbolAddress((void**)&Sp,   g_S);
    cudaGetSymbolAddress((void**)&AGGp, g_AGG);
    cudaGetSymbolAddress((void**)&Up,   g_U);

    const int gx = (NN + 127) / 128;
    const dim3 gWide(gx, 2);   // NC=256 kernels
    const dim3 gNarrow(gx, 1); // NC=128 kernels

    // 1) P_s = x @ We1[0:128], P_r = x @ We1[128:256]
    gemm_fused<128, 0><<<gWide, 256>>>(
        node_inp, nullptr, We1, 256,
        nullptr, 1.0f, nullptr, nullptr, nullptr, nullptr, Pp, 512, 0);
    gemm_fused<128, 0><<<gWide, 256>>>(
        node_inp, nullptr, We1 + 128 * 256, 256,
        nullptr, 1.0f, nullptr, nullptr, nullptr, nullptr, Pp, 512, 256);

    // 2) per-edge swish + segment sum -> S[N,256]
    edge_kernel<<<NN / NPB, 256>>>(edge_feat, senders, We1, be1);

    // 3) agg = LN(S @ We2 / 16 + be2; g_msg, b_msg) * mask
    gemm_fused<256, 1><<<gNarrow, 256>>>(
        Sp, nullptr, We2, 128,
        be2, 1.0f / 16.0f, g_msg, b_msg, node_mask, nullptr, AGGp, 128, 0);

    // 4) U = swish([node_inp, agg] @ Wn1 + bn1)
    gemm_fused<256, 2><<<gWide, 256>>>(
        node_inp, AGGp, Wn1, 256,
        bn1, 1.0f, nullptr, nullptr, nullptr, nullptr, Up, 256, 0);

    // 5) out = LN(node_inp + U @ Wn2 + bn2; g_node, b_node) * mask
    gemm_fused<256, 3><<<gNarrow, 256>>>(
        Up, nullptr, Wn2, 128,
        bn2, 1.0f, g_node, b_node, node_mask, node_inp, out, 128, 0);
}

// round 5
// speedup vs baseline: 1.8903x; 1.0685x over previous
#include <cuda_runtime.h>

#define NN   50000
#define DEG  16
#define DIM  128
#define EDIM 32
#define HDIM 256   // 2*DIM
#define NPB  8     // nodes per block in edge kernel

// ---- scratch (device globals; no allocation allowed) ----
__device__ float g_P[(size_t)NN * 512];  // [N,512]: 0..255 = P_s, 256..511 = P_r
__device__ float g_S[(size_t)NN * HDIM]; // [N,256]: sum over 16 edges of swish(h_pre)
__device__ float g_AGG[(size_t)NN * DIM];
__device__ float g_U[(size_t)NN * HDIM];

typedef unsigned long long u64;

__device__ __forceinline__ void ffma2(u64& d, u64 a, u64 b) {
    asm("fma.rn.f32x2 %0, %1, %2, %3;" : "=l"(d) : "l"(a), "l"(b), "l"(d));
}
__device__ __forceinline__ u64 packf2(float lo, float hi) {
    u64 r; asm("mov.b64 %0, {%1, %2};" : "=l"(r) : "f"(lo), "f"(hi)); return r;
}
__device__ __forceinline__ u64 dupf2(float v) {
    u64 r; asm("mov.b64 %0, {%1, %1};" : "=l"(r) : "f"(v)); return r;
}
__device__ __forceinline__ float2 unpackf2(u64 v) {
    float2 r; asm("mov.b64 {%0, %1}, %2;" : "=f"(r.x), "=f"(r.y) : "l"(v)); return r;
}
__device__ __forceinline__ u64 addf2(u64 a, u64 b) {
    u64 r; asm("add.rn.f32x2 %0, %1, %2;" : "=l"(r) : "l"(a), "l"(b)); return r;
}
__device__ __forceinline__ float swishf(float v) {
    return __fdividef(v, 1.0f + __expf(-v));
}

// ============================================================================
// Register-tiled SGEMM, 8x8 per thread, inner product via fma.rn.f32x2.
//   Memory pattern IDENTICAL to the proven round-3 kernel:
//   BM=128, BK=16, 256 threads, Asm transposed, Bsm row-major, 4x LDS.128/k.
//   Only the FMA section changes: A row-pairs packed, B scalars duplicated,
//   32 FFMA2 replaces 64 FFMA per k-step.
//   MODE 0: plain store (ldOut/outOff)
//   MODE 1: val=acc*scale+bias; LN(gamma,beta)*mask    [NC=128 only]
//   MODE 2: val=swish(acc+bias); A=concat(A0,A1) on K
//   MODE 3: val=acc+bias+resid; LN(gamma,beta)*mask    [NC=128 only]
// ============================================================================
template<int K, int MODE>
__global__ void __launch_bounds__(256, 2) gemm_fused(
    const float* __restrict__ A0, const float* __restrict__ A1,
    const float* __restrict__ B, int ldB,
    const float* __restrict__ bias, float scale,
    const float* __restrict__ gamma, const float* __restrict__ beta,
    const float* __restrict__ mask, const float* __restrict__ resid,
    float* __restrict__ out, int ldOut, int outOff)
{
    constexpr int BM = 128;
    constexpr int BK = 16;

    __shared__ __align__(16) float Asm[BK][BM + 4];   // transposed A tile
    __shared__ __align__(16) float Bsm[BK][128];

    const int tid  = threadIdx.x;
    const int ty   = tid >> 4;        // 0..15
    const int tx   = tid & 15;        // 0..15
    const int n0   = blockIdx.x * BM;
    const int coff = blockIdx.y * 128;

    u64 acc2[4][8];                   // row-pair p (rows 2p,2p+1) x col j
    #pragma unroll
    for (int p = 0; p < 4; p++)
        #pragma unroll
        for (int j = 0; j < 8; j++) acc2[p][j] = 0ull;

    for (int kb = 0; kb < K; kb += BK) {
        // ---- stage A (transposed): 512 float4, 2 per thread ----
        #pragma unroll
        for (int s = 0; s < 2; s++) {
            int idx = tid + s * 256;
            int row = idx >> 2, q = idx & 3;
            int grow = n0 + row;
            float4 a4 = make_float4(0.f, 0.f, 0.f, 0.f);
            if (grow < NN) {
                int gk = kb + q * 4;
                if (MODE == 2)
                    a4 = (gk < DIM)
                       ? *reinterpret_cast<const float4*>(&A0[(size_t)grow * DIM + gk])
                       : *reinterpret_cast<const float4*>(&A1[(size_t)grow * DIM + (gk - DIM)]);
                else
                    a4 = *reinterpret_cast<const float4*>(&A0[(size_t)grow * K + gk]);
            }
            Asm[q * 4 + 0][row] = a4.x;
            Asm[q * 4 + 1][row] = a4.y;
            Asm[q * 4 + 2][row] = a4.z;
            Asm[q * 4 + 3][row] = a4.w;
        }
        // ---- stage B: 512 float4, 2 per thread ----
        #pragma unroll
        for (int s = 0; s < 2; s++) {
            int idx = tid + s * 256;
            int k = idx >> 5, c4 = idx & 31;
            float4 b4 = *reinterpret_cast<const float4*>(&B[(size_t)(kb + k) * ldB + coff + c4 * 4]);
            *reinterpret_cast<float4*>(&Bsm[k][c4 * 4]) = b4;
        }
        __syncthreads();

        #pragma unroll
        for (int kk = 0; kk < BK; kk++) {
            float4 a0 = *reinterpret_cast<const float4*>(&Asm[kk][ty * 8]);
            float4 a1 = *reinterpret_cast<const float4*>(&Asm[kk][ty * 8 + 4]);
            float4 b0 = *reinterpret_cast<const float4*>(&Bsm[kk][tx * 8]);
            float4 b1 = *reinterpret_cast<const float4*>(&Bsm[kk][tx * 8 + 4]);
            u64 apair[4];
            apair[0] = packf2(a0.x, a0.y);
            apair[1] = packf2(a0.z, a0.w);
            apair[2] = packf2(a1.x, a1.y);
            apair[3] = packf2(a1.z, a1.w);
            u64 bdup[8];
            bdup[0] = dupf2(b0.x); bdup[1] = dupf2(b0.y);
            bdup[2] = dupf2(b0.z); bdup[3] = dupf2(b0.w);
            bdup[4] = dupf2(b1.x); bdup[5] = dupf2(b1.y);
            bdup[6] = dupf2(b1.z); bdup[7] = dupf2(b1.w);
            #pragma unroll
            for (int p = 0; p < 4; p++)
                #pragma unroll
                for (int j = 0; j < 8; j++)
                    ffma2(acc2[p][j], apair[p], bdup[j]);
        }
        __syncthreads();
    }

    // unpack row-pairs -> acc[8][8] (register moves only)
    float acc[8][8];
    #pragma unroll
    for (int p = 0; p < 4; p++)
        #pragma unroll
        for (int j = 0; j < 8; j++) {
            float2 v = unpackf2(acc2[p][j]);
            acc[2 * p][j]     = v.x;
            acc[2 * p + 1][j] = v.y;
        }

    // ------------------ epilogue (identical to round 3) ------------------
    const int cbase = coff + tx * 8;

    if (MODE == 0) {
        #pragma unroll
        for (int r = 0; r < 8; r++) {
            int row = n0 + ty * 8 + r;
            if (row < NN) {
                float* o = &out[(size_t)row * ldOut + outOff + cbase];
                *reinterpret_cast<float4*>(o)     = make_float4(acc[r][0], acc[r][1], acc[r][2], acc[r][3]);
                *reinterpret_cast<float4*>(o + 4) = make_float4(acc[r][4], acc[r][5], acc[r][6], acc[r][7]);
            }
        }
        return;
    }
    if (MODE == 2) {
        float be[8];
        #pragma unroll
        for (int j = 0; j < 8; j++) be[j] = bias[cbase + j];
        #pragma unroll
        for (int r = 0; r < 8; r++) {
            int row = n0 + ty * 8 + r;
            if (row < NN) {
                float v[8];
                #pragma unroll
                for (int j = 0; j < 8; j++) v[j] = swishf(acc[r][j] + be[j]);
                float* o = &out[(size_t)row * ldOut + cbase];
                *reinterpret_cast<float4*>(o)     = make_float4(v[0], v[1], v[2], v[3]);
                *reinterpret_cast<float4*>(o + 4) = make_float4(v[4], v[5], v[6], v[7]);
            }
        }
        return;
    }
    // LN modes (NC=128, coff=0): 16 tx-threads cover the full 128-wide row.
    {
        float be[8], gm[8], bt[8];
        #pragma unroll
        for (int j = 0; j < 8; j++) {
            be[j] = bias[cbase + j]; gm[j] = gamma[cbase + j]; bt[j] = beta[cbase + j];
        }
        #pragma unroll
        for (int r = 0; r < 8; r++) {
            int row = n0 + ty * 8 + r;
            float v[8];
            #pragma unroll
            for (int j = 0; j < 8; j++) v[j] = acc[r][j] * scale + be[j];
            if (MODE == 3 && row < NN) {
                float4 r0 = *reinterpret_cast<const float4*>(&resid[(size_t)row * 128 + cbase]);
                float4 r1 = *reinterpret_cast<const float4*>(&resid[(size_t)row * 128 + cbase + 4]);
                v[0] += r0.x; v[1] += r0.y; v[2] += r0.z; v[3] += r0.w;
                v[4] += r1.x; v[5] += r1.y; v[6] += r1.z; v[7] += r1.w;
            }
            float s = 0.f, s2 = 0.f;
            #pragma unroll
            for (int j = 0; j < 8; j++) { s += v[j]; s2 += v[j] * v[j]; }
            #pragma unroll
            for (int o = 8; o > 0; o >>= 1) {
                s  += __shfl_xor_sync(0xffffffffu, s,  o);
                s2 += __shfl_xor_sync(0xffffffffu, s2, o);
            }
            float m    = s * (1.0f / 128.0f);
            float var  = s2 * (1.0f / 128.0f) - m * m;
            float rstd = rsqrtf(var + 1e-5f);
            if (row < NN) {
                float mk = mask[row];
                float w[8];
                #pragma unroll
                for (int j = 0; j < 8; j++)
                    w[j] = ((v[j] - m) * rstd * gm[j] + bt[j]) * mk;
                float* o = &out[(size_t)row * 128 + cbase];
                *reinterpret_cast<float4*>(o)     = make_float4(w[0], w[1], w[2], w[3]);
                *reinterpret_cast<float4*>(o + 4) = make_float4(w[4], w[5], w[6], w[7]);
            }
        }
    }
}

// ============================================================================
// Edge kernel (f32x2 over edge pairs; verified correct in round 2):
//   h_e = swish(P_s[senders[e]] + P_r[n] + ef[e]@We1[256:288] + be1)
//   S[n] = sum_e h_e      (16 contiguous edges per node)
// 256 threads = 256 output channels; NPB nodes per block.
// Edge features pre-packed into (even-edge, odd-edge) f32x2 pairs in smem;
// compute reads are broadcast LDS.128. Weight dup pairs live in registers
// OUTSIDE all loops (zero per-iteration cost). 32 FFMA2 per edge pair.
// ============================================================================
__global__ void __launch_bounds__(256, 2) edge_kernel(
    const float* __restrict__ edge_feat, const int* __restrict__ senders,
    const float* __restrict__ We1, const float* __restrict__ be1)
{
    __shared__ __align__(16) u64 efp[NPB * (DEG / 2) * EDIM];  // 16 KB, pair-packed
    __shared__ int snd[NPB * DEG];

    const int t  = threadIdx.x;
    const int n0 = blockIdx.x * NPB;
    const int cnt = min(NPB, NN - n0);
    const int e0 = n0 * DEG;

    // load edge features, pack edge pairs into f32x2 lanes
    {
        const int totf = cnt * DEG * EDIM;
        float* efs = reinterpret_cast<float*>(efp);
        for (int j = t; j < totf; j += 256) {
            int el = j / EDIM, k = j % EDIM;
            int pg = el >> 1, half = el & 1;
            efs[(pg * EDIM + k) * 2 + half] = edge_feat[(size_t)e0 * EDIM + j];
        }
        for (int j = t; j < cnt * DEG; j += 256) snd[j] = senders[e0 + j];
    }

    // duplicated weight column for this channel: w2[k] = (w[k], w[k])
    u64 w2[EDIM];
    #pragma unroll
    for (int k = 0; k < EDIM; k++)
        w2[k] = dupf2(We1[(size_t)(HDIM + k) * HDIM + t]);
    const float b1 = be1[t];
    __syncthreads();

    for (int ni = 0; ni < cnt; ni++) {
        const int n = n0 + ni;
        const float pr = g_P[(size_t)n * 512 + 256 + t] + b1;
        const u64 prd = dupf2(pr);

        // prefetch all 16 sender projections (deep MLP hides L2 latency)
        float fv[DEG];
        #pragma unroll
        for (int e = 0; e < DEG; e++)
            fv[e] = g_P[(size_t)snd[ni * DEG + e] * 512 + t];

        float sacc = 0.0f;
        #pragma unroll
        for (int p = 0; p < DEG / 2; p++) {
            u64 v2 = addf2(prd, packf2(fv[2 * p], fv[2 * p + 1]));
            const ulonglong2* ep =
                reinterpret_cast<const ulonglong2*>(&efp[(ni * (DEG / 2) + p) * EDIM]);
            #pragma unroll
            for (int q = 0; q < EDIM / 2; q++) {
                ulonglong2 e2 = ep[q];
                ffma2(v2, e2.x, w2[2 * q]);
                ffma2(v2, e2.y, w2[2 * q + 1]);
            }
            float2 v = unpackf2(v2);
            sacc += swishf(v.x) + swishf(v.y);
        }
        g_S[(size_t)n * HDIM + t] = sacc;
    }
}

// ============================================================================
extern "C" void kernel_launch(void* const* d_in, const int* in_sizes, int n_in,
                              void* d_out, int out_size)
{
    const float* node_inp  = (const float*)d_in[0];
    const float* edge_feat = (const float*)d_in[1];
    const float* node_mask = (const float*)d_in[2];
    const float* We1       = (const float*)d_in[3];
    const float* be1       = (const float*)d_in[4];
    const float* We2       = (const float*)d_in[5];
    const float* be2       = (const float*)d_in[6];
    const float* g_msg     = (const float*)d_in[7];
    const float* b_msg     = (const float*)d_in[8];
    const float* Wn1       = (const float*)d_in[9];
    const float* bn1       = (const float*)d_in[10];
    const float* Wn2       = (const float*)d_in[11];
    const float* bn2       = (const float*)d_in[12];
    const float* g_node    = (const float*)d_in[13];
    const float* b_node    = (const float*)d_in[14];
    const int*   senders   = (const int*)d_in[15];
    float* out = (float*)d_out;

    float *Pp, *Sp, *AGGp, *Up;
    cudaGetSymbolAddress((void**)&Pp,   g_P);
    cudaGetSymbolAddress((void**)&Sp,   g_S);
    cudaGetSymbolAddress((void**)&AGGp, g_AGG);
    cudaGetSymbolAddress((void**)&Up,   g_U);

    const int gx = (NN + 127) / 128;
    const dim3 gWide(gx, 2);   // NC=256 kernels
    const dim3 gNarrow(gx, 1); // NC=128 kernels

    // 1) P_s = x @ We1[0:128], P_r = x @ We1[128:256]
    gemm_fused<128, 0><<<gWide, 256>>>(
        node_inp, nullptr, We1, 256,
        nullptr, 1.0f, nullptr, nullptr, nullptr, nullptr, Pp, 512, 0);
    gemm_fused<128, 0><<<gWide, 256>>>(
        node_inp, nullptr, We1 + 128 * 256, 256,
        nullptr, 1.0f, nullptr, nullptr, nullptr, nullptr, Pp, 512, 256);

    // 2) per-edge swish + segment sum -> S[N,256]
    edge_kernel<<<NN / NPB, 256>>>(edge_feat, senders, We1, be1);

    // 3) agg = LN(S @ We2 / 16 + be2; g_msg, b_msg) * mask
    gemm_fused<256, 1><<<gNarrow, 256>>>(
        Sp, nullptr, We2, 128,
        be2, 1.0f / 16.0f, g_msg, b_msg, node_mask, nullptr, AGGp, 128, 0);

    // 4) U = swish([node_inp, agg] @ Wn1 + bn1)
    gemm_fused<256, 2><<<gWide, 256>>>(
        node_inp, AGGp, Wn1, 256,
        bn1, 1.0f, nullptr, nullptr, nullptr, nullptr, Up, 256, 0);

    // 5) out = LN(node_inp + U @ Wn2 + bn2; g_node, b_node) * mask
    gemm_fused<256, 3><<<gNarrow, 256>>>(
        Up, nullptr, Wn2, 128,
        bn2, 1.0f, g_node, b_node, node_mask, node_inp, out, 128, 0);
}

// round 6
// speedup vs baseline: 2.0774x; 1.0990x over previous
#include <cuda_runtime.h>
#include <cuda_bf16.h>
#include <cstdint>

#define NN   50000
#define NP   50048     // 391*128 padded rows
#define DEG  16
#define DIM  128
#define EDIM 32
#define HDIM 256
#define NPB  8
#define GX   391

typedef unsigned long long u64;

// ---- scratch (device globals; no allocation allowed) ----
__device__ float g_P[(size_t)NN * 512];                 // fp32 projections (edge gathers)
__device__ __nv_bfloat16 g_NAh[(size_t)NP * 256];       // cols 0-127 node_inp, 128-255 AGG
__device__ __nv_bfloat16 g_NAl[(size_t)NP * 256];
__device__ __nv_bfloat16 g_Sh[(size_t)NP * 256];        // edge-sum S
__device__ __nv_bfloat16 g_Sl[(size_t)NP * 256];
__device__ __nv_bfloat16 g_Uh[(size_t)NP * 256];        // node-MLP hidden U
__device__ __nv_bfloat16 g_Ul[(size_t)NP * 256];
__device__ __nv_bfloat16 g_Wh[196608];                  // weights, [n][K] per region
__device__ __nv_bfloat16 g_Wl[196608];

__device__ __forceinline__ float swishf(float v) {
    return __fdividef(v, 1.0f + __expf(-v));
}
__device__ __forceinline__ uint32_t smem_u32(const void* p) {
    uint32_t a;
    asm("{ .reg .u64 t; cvta.to.shared.u64 t, %1; cvt.u32.u64 %0, t; }" : "=r"(a) : "l"(p));
    return a;
}
__device__ __forceinline__ void ldsm4(uint32_t& r0, uint32_t& r1, uint32_t& r2,
                                      uint32_t& r3, uint32_t addr) {
    asm volatile("ldmatrix.sync.aligned.m8n8.x4.shared.b16 {%0,%1,%2,%3}, [%4];"
                 : "=r"(r0), "=r"(r1), "=r"(r2), "=r"(r3) : "r"(addr));
}
__device__ __forceinline__ void mma16816(float* c, const uint32_t* a, const uint32_t* b) {
    asm volatile("mma.sync.aligned.m16n8k16.row.col.f32.bf16.bf16.f32 "
                 "{%0,%1,%2,%3}, {%4,%5,%6,%7}, {%8,%9}, {%0,%1,%2,%3};"
                 : "+f"(c[0]), "+f"(c[1]), "+f"(c[2]), "+f"(c[3])
                 : "r"(a[0]), "r"(a[1]), "r"(a[2]), "r"(a[3]), "r"(b[0]), "r"(b[1]));
}
__device__ __forceinline__ void split_store(__nv_bfloat16* dh, __nv_bfloat16* dl,
                                            size_t pos, float v0, float v1) {
    __nv_bfloat16 h0 = __float2bfloat16(v0), h1 = __float2bfloat16(v1);
    __nv_bfloat162 hp; hp.x = h0; hp.y = h1;
    *reinterpret_cast<__nv_bfloat162*>(&dh[pos]) = hp;
    __nv_bfloat162 lp;
    lp.x = __float2bfloat16(v0 - __bfloat162float(h0));
    lp.y = __float2bfloat16(v1 - __bfloat162float(h1));
    *reinterpret_cast<__nv_bfloat162*>(&dl[pos]) = lp;
}

// ============================================================================
// prep kernels
// ============================================================================
// node_inp -> g_NA cols 0-127 (split bf16). grid=NN, block=64.
__global__ void conv_node(const float* __restrict__ x) {
    int row = blockIdx.x, t = threadIdx.x;
    float2 v = *reinterpret_cast<const float2*>(&x[(size_t)row * 128 + 2 * t]);
    split_store(g_NAh, g_NAl, (size_t)row * 256 + 2 * t, v.x, v.y);
}
// weight prep: dst[n*K + k] = split(src[(rowOff+k)*ld + n]); dst region [NCtot][K]
__global__ void wprep(const float* __restrict__ src, int ld, int rowOff, int K,
                      __nv_bfloat16* __restrict__ dh, __nv_bfloat16* __restrict__ dl,
                      int total) {
    int idx = blockIdx.x * 256 + threadIdx.x;
    if (idx >= total) return;
    int n = idx / K, k = idx % K;
    float v = src[(size_t)(rowOff + k) * ld + n];
    __nv_bfloat16 h = __float2bfloat16(v);
    dh[idx] = h;
    dl[idx] = __float2bfloat16(v - __bfloat162float(h));
}

// ============================================================================
// Split-bf16 HMMA GEMM: C[M,NC] = A[M,K]@B[K,NC], M-tile 128, N-tile 128.
//   A: global split-bf16 [NP][256] row-major (cols kb..). B: [NCtot][K] n-major.
//   256 thr = 8 warps (wm=warp&3 row 32s, wn=warp>>2 col 64s). BK=32.
//   3-term split: Ah*Bh + Ah*Bl + Al*Bh -> fp32 acc. Epilogue via smem Csm.
//   MODE 0: fp32 store (ldOut, col by*128)
//   MODE 1: v=acc*scale+bias; LN*mask -> split bf16 g_NA cols 128..255
//   MODE 2: v=swish(acc+bias)        -> split bf16 oB cols by*128..
//   MODE 3: v=acc+bias+resid; LN*mask -> fp32 out
// ============================================================================
template<int K, int MODE>
__global__ void __launch_bounds__(256, 2) mma_gemm(
    const __nv_bfloat16* __restrict__ Ah, const __nv_bfloat16* __restrict__ Al,
    const __nv_bfloat16* __restrict__ Bh, const __nv_bfloat16* __restrict__ Bl,
    const float* __restrict__ bias, float scale,
    const float* __restrict__ gamma, const float* __restrict__ beta,
    const float* __restrict__ mask, const float* __restrict__ resid,
    float* __restrict__ outF, int ldOut,
    __nv_bfloat16* __restrict__ oBh, __nv_bfloat16* __restrict__ oBl, int oCol)
{
    extern __shared__ __align__(16) char smem[];
    __nv_bfloat16* sAh = reinterpret_cast<__nv_bfloat16*>(smem);           // [128][40]
    __nv_bfloat16* sAl = sAh + 5120;
    __nv_bfloat16* sBh = sAh + 10240;                                      // [128n][40k]
    __nv_bfloat16* sBl = sAh + 15360;
    float* Csm = reinterpret_cast<float*>(smem);                           // [128][132]

    const uint32_t sb = smem_u32(smem);
    const int t = threadIdx.x, lane = t & 31, warp = t >> 5;
    const int wm = warp & 3, wn = warp >> 2;
    const int n0 = blockIdx.x * 128, by = blockIdx.y;

    float acc[2][8][4];
    #pragma unroll
    for (int mt = 0; mt < 2; mt++)
        #pragma unroll
        for (int nt = 0; nt < 8; nt++)
            #pragma unroll
            for (int q = 0; q < 4; q++) acc[mt][nt][q] = 0.f;

    for (int kb = 0; kb < K; kb += 32) {
        // ---- stage 4 tiles: 512 uint4 each, 2 per thread ----
        #pragma unroll
        for (int s = 0; s < 2; s++) {
            int idx = t + s * 256;
            int row = idx >> 2, g = idx & 3;
            int grow = n0 + row;
            uint4 zh = make_uint4(0u, 0u, 0u, 0u), zl = zh;
            if (grow < NN) {
                size_t ap = (size_t)grow * 256 + kb + g * 8;
                zh = *reinterpret_cast<const uint4*>(&Ah[ap]);
                zl = *reinterpret_cast<const uint4*>(&Al[ap]);
            }
            int so = row * 40 + g * 8;
            *reinterpret_cast<uint4*>(&sAh[so]) = zh;
            *reinterpret_cast<uint4*>(&sAl[so]) = zl;
            size_t bp = (size_t)(by * 128 + row) * K + kb + g * 8;
            *reinterpret_cast<uint4*>(&sBh[so]) = *reinterpret_cast<const uint4*>(&Bh[bp]);
            *reinterpret_cast<uint4*>(&sBl[so]) = *reinterpret_cast<const uint4*>(&Bl[bp]);
        }
        __syncthreads();

        #pragma unroll
        for (int kt = 0; kt < 32; kt += 16) {
            uint32_t ah[2][4], al[2][4];
            {
                int ar = lane & 15, as_ = (lane >> 4) * 8;
                #pragma unroll
                for (int mt = 0; mt < 2; mt++) {
                    uint32_t off = (uint32_t)((wm * 32 + mt * 16 + ar) * 40 + kt + as_) * 2;
                    ldsm4(ah[mt][0], ah[mt][1], ah[mt][2], ah[mt][3], sb + off);
                    ldsm4(al[mt][0], al[mt][1], al[mt][2], al[mt][3], sb + 10240 + off);
                }
            }
            #pragma unroll
            for (int p = 0; p < 4; p++) {
                int sel = lane >> 3, i = lane & 7;
                uint32_t boff = (uint32_t)((wn * 64 + p * 16 + ((sel >> 1) << 3) + i) * 40
                                           + kt + ((sel & 1) << 3)) * 2;
                uint32_t bh[4], bl[4];
                ldsm4(bh[0], bh[1], bh[2], bh[3], sb + 20480 + boff);
                ldsm4(bl[0], bl[1], bl[2], bl[3], sb + 30720 + boff);
                #pragma unroll
                for (int mt = 0; mt < 2; mt++)
                    #pragma unroll
                    for (int q = 0; q < 2; q++) {
                        float* c = acc[mt][2 * p + q];
                        mma16816(c, ah[mt], &bh[2 * q]);
                        mma16816(c, ah[mt], &bl[2 * q]);
                        mma16816(c, al[mt], &bh[2 * q]);
                    }
            }
        }
        __syncthreads();
    }

    // ---- fragments -> Csm ----
    {
        int g = lane >> 2, cc = (lane & 3) * 2;
        #pragma unroll
        for (int mt = 0; mt < 2; mt++)
            #pragma unroll
            for (int nt = 0; nt < 8; nt++) {
                int r0 = wm * 32 + mt * 16 + g;
                int col = wn * 64 + nt * 8 + cc;
                *reinterpret_cast<float2*>(&Csm[r0 * 132 + col]) =
                    make_float2(acc[mt][nt][0], acc[mt][nt][1]);
                *reinterpret_cast<float2*>(&Csm[(r0 + 8) * 132 + col]) =
                    make_float2(acc[mt][nt][2], acc[mt][nt][3]);
            }
    }
    __syncthreads();

    // ---- epilogue: 2 threads per row (64 cols each) ----
    const int r = t >> 1, hh = t & 1, ch0 = hh * 64;
    const int row = n0 + r;
    const float* crow = &Csm[r * 132 + ch0];

    if (MODE == 0) {
        if (row < NN) {
            float* o = &outF[(size_t)row * ldOut + by * 128 + ch0];
            #pragma unroll
            for (int j = 0; j < 64; j += 4)
                *reinterpret_cast<float4*>(&o[j]) = *reinterpret_cast<const float4*>(&crow[j]);
        }
        return;
    }
    if (MODE == 2) {
        if (row < NN) {
            #pragma unroll
            for (int j = 0; j < 64; j += 2) {
                int c = by * 128 + ch0 + j;
                float v0 = swishf(crow[j]     + bias[c]);
                float v1 = swishf(crow[j + 1] + bias[c + 1]);
                split_store(oBh, oBl, (size_t)row * 256 + c, v0, v1);
            }
        }
        return;
    }
    // LN modes (NC=128, by=0)
    {
        float s = 0.f, s2 = 0.f;
        #pragma unroll
        for (int j = 0; j < 64; j += 4) {
            float4 c4 = *reinterpret_cast<const float4*>(&crow[j]);
            float v0 = c4.x * scale + bias[ch0 + j];
            float v1 = c4.y * scale + bias[ch0 + j + 1];
            float v2 = c4.z * scale + bias[ch0 + j + 2];
            float v3 = c4.w * scale + bias[ch0 + j + 3];
            if (MODE == 3 && row < NN) {
                float4 r4 = *reinterpret_cast<const float4*>(&resid[(size_t)row * 128 + ch0 + j]);
                v0 += r4.x; v1 += r4.y; v2 += r4.z; v3 += r4.w;
            }
            s += v0 + v1 + v2 + v3;
            s2 += v0 * v0 + v1 * v1 + v2 * v2 + v3 * v3;
        }
        s  += __shfl_xor_sync(0xffffffffu, s, 1);
        s2 += __shfl_xor_sync(0xffffffffu, s2, 1);
        float m    = s * (1.0f / 128.0f);
        float var  = s2 * (1.0f / 128.0f) - m * m;
        float rstd = rsqrtf(var + 1e-5f);
        if (row < NN) {
            float mk = mask[row];
            #pragma unroll
            for (int j = 0; j < 64; j += 2) {
                int c = ch0 + j;
                float v0 = crow[j]     * scale + bias[c];
                float v1 = crow[j + 1] * scale + bias[c + 1];
                if (MODE == 3) {
                    float2 r2 = *reinterpret_cast<const float2*>(&resid[(size_t)row * 128 + c]);
                    v0 += r2.x; v1 += r2.y;
                }
                float w0 = ((v0 - m) * rstd * gamma[c]     + beta[c])     * mk;
                float w1 = ((v1 - m) * rstd * gamma[c + 1] + beta[c + 1]) * mk;
                if (MODE == 3) {
                    *reinterpret_cast<float2*>(&outF[(size_t)row * 128 + c]) = make_float2(w0, w1);
                } else {
                    split_store(oBh, oBl, (size_t)row * 256 + oCol + c, w0, w1);
                }
            }
        }
    }
}

// ============================================================================
// Edge kernel (round-5 proven body; output now split bf16):
//   h_e = swish(P_s[senders[e]] + P_r[n] + ef[e]@We1[256:288] + be1)
//   S[n] = sum_e h_e
// ============================================================================
__device__ __forceinline__ void ffma2(u64& d, u64 a, u64 b) {
    asm("fma.rn.f32x2 %0, %1, %2, %3;" : "=l"(d) : "l"(a), "l"(b), "l"(d));
}
__device__ __forceinline__ u64 packf2(float lo, float hi) {
    u64 r; asm("mov.b64 %0, {%1, %2};" : "=l"(r) : "f"(lo), "f"(hi)); return r;
}
__device__ __forceinline__ u64 dupf2(float v) {
    u64 r; asm("mov.b64 %0, {%1, %1};" : "=l"(r) : "f"(v)); return r;
}
__device__ __forceinline__ float2 unpackf2(u64 v) {
    float2 r; asm("mov.b64 {%0, %1}, %2;" : "=f"(r.x), "=f"(r.y) : "l"(v)); return r;
}
__device__ __forceinline__ u64 addf2(u64 a, u64 b) {
    u64 r; asm("add.rn.f32x2 %0, %1, %2;" : "=l"(r) : "l"(a), "l"(b)); return r;
}

__global__ void __launch_bounds__(256, 2) edge_kernel(
    const float* __restrict__ edge_feat, const int* __restrict__ senders,
    const float* __restrict__ We1, const float* __restrict__ be1)
{
    __shared__ __align__(16) u64 efp[NPB * (DEG / 2) * EDIM];
    __shared__ int snd[NPB * DEG];

    const int t  = threadIdx.x;
    const int n0 = blockIdx.x * NPB;
    const int cnt = min(NPB, NN - n0);
    const int e0 = n0 * DEG;

    {
        const int totf = cnt * DEG * EDIM;
        float* efs = reinterpret_cast<float*>(efp);
        for (int j = t; j < totf; j += 256) {
            int el = j / EDIM, k = j % EDIM;
            int pg = el >> 1, half = el & 1;
            efs[(pg * EDIM + k) * 2 + half] = edge_feat[(size_t)e0 * EDIM + j];
        }
        for (int j = t; j < cnt * DEG; j += 256) snd[j] = senders[e0 + j];
    }

    u64 w2[EDIM];
    #pragma unroll
    for (int k = 0; k < EDIM; k++)
        w2[k] = dupf2(We1[(size_t)(HDIM + k) * HDIM + t]);
    const float b1 = be1[t];
    __syncthreads();

    for (int ni = 0; ni < cnt; ni++) {
        const int n = n0 + ni;
        const float pr = g_P[(size_t)n * 512 + 256 + t] + b1;
        const u64 prd = dupf2(pr);

        float fv[DEG];
        #pragma unroll
        for (int e = 0; e < DEG; e++)
            fv[e] = g_P[(size_t)snd[ni * DEG + e] * 512 + t];

        float sacc = 0.0f;
        #pragma unroll
        for (int p = 0; p < DEG / 2; p++) {
            u64 v2 = addf2(prd, packf2(fv[2 * p], fv[2 * p + 1]));
            const ulonglong2* ep =
                reinterpret_cast<const ulonglong2*>(&efp[(ni * (DEG / 2) + p) * EDIM]);
            #pragma unroll
            for (int q = 0; q < EDIM / 2; q++) {
                ulonglong2 e2 = ep[q];
                ffma2(v2, e2.x, w2[2 * q]);
                ffma2(v2, e2.y, w2[2 * q + 1]);
            }
            float2 v = unpackf2(v2);
            sacc += swishf(v.x) + swishf(v.y);
        }
        __nv_bfloat16 h = __float2bfloat16(sacc);
        g_Sh[(size_t)n * 256 + t] = h;
        g_Sl[(size_t)n * 256 + t] = __float2bfloat16(sacc - __bfloat162float(h));
    }
}

// ============================================================================
extern "C" void kernel_launch(void* const* d_in, const int* in_sizes, int n_in,
                              void* d_out, int out_size)
{
    const float* node_inp  = (const float*)d_in[0];
    const float* edge_feat = (const float*)d_in[1];
    const float* node_mask = (const float*)d_in[2];
    const float* We1       = (const float*)d_in[3];
    const float* be1       = (const float*)d_in[4];
    const float* We2       = (const float*)d_in[5];
    const float* be2       = (const float*)d_in[6];
    const float* g_msg     = (const float*)d_in[7];
    const float* b_msg     = (const float*)d_in[8];
    const float* Wn1       = (const float*)d_in[9];
    const float* bn1       = (const float*)d_in[10];
    const float* Wn2       = (const float*)d_in[11];
    const float* bn2       = (const float*)d_in[12];
    const float* g_node    = (const float*)d_in[13];
    const float* b_node    = (const float*)d_in[14];
    const int*   senders   = (const int*)d_in[15];
    float* out = (float*)d_out;

    float* Pp;
    __nv_bfloat16 *NAh, *NAl, *Sh, *Sl, *Uh, *Ul, *Wh, *Wl;
    cudaGetSymbolAddress((void**)&Pp,  g_P);
    cudaGetSymbolAddress((void**)&NAh, g_NAh);
    cudaGetSymbolAddress((void**)&NAl, g_NAl);
    cudaGetSymbolAddress((void**)&Sh,  g_Sh);
    cudaGetSymbolAddress((void**)&Sl,  g_Sl);
    cudaGetSymbolAddress((void**)&Uh,  g_Uh);
    cudaGetSymbolAddress((void**)&Ul,  g_Ul);
    cudaGetSymbolAddress((void**)&Wh,  g_Wh);
    cudaGetSymbolAddress((void**)&Wl,  g_Wl);

    const int SMEMT = 67584;  // 128*132*4 (covers operand tiles 40960B too)
    cudaFuncSetAttribute(mma_gemm<128,0>, cudaFuncAttributeMaxDynamicSharedMemorySize, SMEMT);
    cudaFuncSetAttribute(mma_gemm<256,1>, cudaFuncAttributeMaxDynamicSharedMemorySize, SMEMT);
    cudaFuncSetAttribute(mma_gemm<256,2>, cudaFuncAttributeMaxDynamicSharedMemorySize, SMEMT);
    cudaFuncSetAttribute(mma_gemm<256,3>, cudaFuncAttributeMaxDynamicSharedMemorySize, SMEMT);

    // ---- weight prep: regions [NCtot][K] ----
    // W1 @0: [512][128] = [We1[0:128,:] ; We1[128:256,:]]
    wprep<<<128, 256>>>(We1, 256,   0, 128, Wh,          Wl,          32768);
    wprep<<<128, 256>>>(We1, 256, 128, 128, Wh + 32768,  Wl + 32768,  32768);
    // W2 @65536: [128][256] from We2[256,128]
    wprep<<<128, 256>>>(We2, 128,   0, 256, Wh + 65536,  Wl + 65536,  32768);
    // W3 @98304: [256][256] from Wn1[256,256]
    wprep<<<256, 256>>>(Wn1, 256,   0, 256, Wh + 98304,  Wl + 98304,  65536);
    // W4 @163840: [128][256] from Wn2[256,128]
    wprep<<<128, 256>>>(Wn2, 128,   0, 256, Wh + 163840, Wl + 163840, 32768);

    // ---- node_inp -> g_NA cols 0..127 ----
    conv_node<<<NN, 64>>>(node_inp);

    // 1) P = node_inp @ [We1_s | We1_r] -> g_P fp32 [N,512]
    mma_gemm<128,0><<<dim3(GX, 4), 256, SMEMT>>>(
        NAh, NAl, Wh, Wl,
        nullptr, 1.0f, nullptr, nullptr, nullptr, nullptr, Pp, 512, nullptr, nullptr, 0);

    // 2) per-edge swish + segment sum -> S (split bf16)
    edge_kernel<<<NN / NPB, 256>>>(edge_feat, senders, We1, be1);

    // 3) agg = LN(S @ We2 /16 + be2; g_msg,b_msg)*mask -> g_NA cols 128..255
    mma_gemm<256,1><<<dim3(GX, 1), 256, SMEMT>>>(
        Sh, Sl, Wh + 65536, Wl + 65536,
        be2, 1.0f / 16.0f, g_msg, b_msg, node_mask, nullptr, nullptr, 0, NAh, NAl, 128);

    // 4) U = swish(NA @ Wn1 + bn1) -> g_U (split bf16)
    mma_gemm<256,2><<<dim3(GX, 2), 256, SMEMT>>>(
        NAh, NAl, Wh + 98304, Wl + 98304,
        bn1, 1.0f, nullptr, nullptr, nullptr, nullptr, nullptr, 0, Uh, Ul, 0);

    // 5) out = LN(node_inp + U @ Wn2 + bn2; g_node,b_node)*mask -> fp32 out
    mma_gemm<256,3><<<dim3(GX, 1), 256, SMEMT>>>(
        Uh, Ul, Wh + 163840, Wl + 163840,
        bn2, 1.0f, g_node, b_node, node_mask, node_inp, out, 128, nullptr, nullptr, 0);
}